// round 12
// baseline (speedup 1.0000x reference)
#include <cuda_runtime.h>
#include <cstdint>

// SwitchLinear via portable mma.sync tf32 + ldmatrix + cp.async (sm_103-safe).
// out[t] = (W[route[t]] + Wf) @ x[t] + b[route[t]] + bf ; B=4096, IN=OUT=256, E=16.
//
// prep (257 blocks): 0..255: g_wsum = cvt.rna.tf32(W + Wf), [e][o][k] layout
//                    (rows are directly the col-major B operand of mma row.col);
//                    block 256: routing into 64-token m-tiles + g_bsum.
// switch_gemm (<=160 blocks, 512 thr): tile = (64 tokens, 128 outs).
//   16 warps (4m x 4n), warp tile 16x32, mma.m16n8k8.tf32, fp32 accum.
//   KC=64, 4 chunks. B: cp.async 3-buffer ring (wait_group(1) + 1 barrier/chunk).
//   A: LDG+cvt+STS double buffer. Fragments via ldmatrix.x4, rows padded to 68
//   floats (odd 16B stride -> LDSM conflict-free).

#define B_TOK   4096
#define E_NUM   16
#define TM      64
#define TN      128
#define KC      64
#define NCH     4
#define MAX_MT  80
#define GRID_GEMM 160
#define RPAD    68                        // 64 + 4 pad floats per row
#define A_TILE_F (TM * RPAD)              // 4352 floats (17408 B)
#define B_TILE_F (TN * RPAD)              // 8704 floats (34816 B)
#define DSMEM_BYTES ((2 * A_TILE_F + 3 * B_TILE_F) * 4)   // 139264 B

__device__ int   g_sorted[B_TOK];
__device__ int   g_mt_e[MAX_MT];
__device__ int   g_mt_base[MAX_MT];
__device__ int   g_mt_cnt[MAX_MT];
__device__ int   g_nmt;
__device__ float g_wsum[E_NUM * 256 * 256];   // [e][o][k], tf32(rna)-rounded
__device__ float g_bsum[E_NUM * 256];

static __device__ __forceinline__ uint32_t smem_u32(const void* p) {
    uint32_t a;
    asm("{ .reg .u64 t; cvta.to.shared.u64 t, %1; cvt.u32.u64 %0, t; }" : "=r"(a) : "l"(p));
    return a;
}
static __device__ __forceinline__ uint32_t f2tf(float x) {
    uint32_t u;
    asm("cvt.rna.tf32.f32 %0, %1;" : "=r"(u) : "f"(x));
    return u;
}
static __device__ __forceinline__ void mma_tf32(float* d, const uint32_t* a,
                                                uint32_t b0, uint32_t b1) {
    asm volatile(
        "mma.sync.aligned.m16n8k8.row.col.f32.tf32.tf32.f32 "
        "{%0,%1,%2,%3}, {%4,%5,%6,%7}, {%8,%9}, {%0,%1,%2,%3};"
        : "+f"(d[0]), "+f"(d[1]), "+f"(d[2]), "+f"(d[3])
        : "r"(a[0]), "r"(a[1]), "r"(a[2]), "r"(a[3]), "r"(b0), "r"(b1));
}
#define LDSM_X4(r0, r1, r2, r3, addr) \
    asm volatile("ldmatrix.sync.aligned.m8n8.x4.shared.b16 {%0,%1,%2,%3}, [%4];" \
                 : "=r"(r0), "=r"(r1), "=r"(r2), "=r"(r3) : "r"(addr))
#define CP_ASYNC16(dst, src) \
    asm volatile("cp.async.cg.shared.global [%0], [%1], 16;" :: "r"(dst), "l"(src))
#define CP_COMMIT() asm volatile("cp.async.commit_group;" ::: "memory")
#define CP_WAIT1()  asm volatile("cp.async.wait_group 1;" ::: "memory")
#define CP_WAIT0()  asm volatile("cp.async.wait_group 0;" ::: "memory")

// ---------------------------------------------------------------------------
// prep: blocks 0..255 Wsum copy+add+round (4096 floats each); block 256 routing
// ---------------------------------------------------------------------------
__global__ void prep_kernel(const int* __restrict__ route,
                            const float* __restrict__ weight,
                            const float* __restrict__ wfact,
                            const float* __restrict__ bias,
                            const float* __restrict__ bfact) {
    const int tid = threadIdx.x;

    if (blockIdx.x < 256) {
        // 256 blocks x 4096 floats = 1,048,576 = E*256*256  (16 blocks/expert)
        const size_t base = (size_t)blockIdx.x * 4096;    // floats
        const int fb = (blockIdx.x & 15) * 4096;          // offset mod 65536
        #pragma unroll
        for (int i = 0; i < 4; i++) {
            int j = (tid + 256 * i) * 4;                  // 0..4092
            float4 w = *(const float4*)(weight + base + j);
            float4 f = *(const float4*)(wfact + fb + j);
            uint4 o;
            o.x = f2tf(w.x + f.x);
            o.y = f2tf(w.y + f.y);
            o.z = f2tf(w.z + f.z);
            o.w = f2tf(w.w + f.w);
            *(uint4*)((float*)g_wsum + base + j) = o;
        }
    } else {
        __shared__ int cnt[E_NUM];
        __shared__ int cur[E_NUM];
        const int lane = tid & 31;
        if (tid < E_NUM) cnt[tid] = 0;
        __syncthreads();

        for (int t = tid; t < B_TOK; t += 256) {
            int e = route[t];
            unsigned m = __match_any_sync(0xffffffffu, e);
            int leader = __ffs(m) - 1;
            if (lane == leader) atomicAdd(&cnt[e], __popc(m));
        }
        __syncthreads();

        if (tid < 32) {
            int c  = (tid < E_NUM) ? cnt[tid] : 0;
            int nt = (c + TM - 1) / TM;
            int cs = c, ts = nt;
            #pragma unroll
            for (int d = 1; d < 32; d <<= 1) {
                int v = __shfl_up_sync(0xffffffffu, cs, d);
                int w = __shfl_up_sync(0xffffffffu, ts, d);
                if (lane >= d) { cs += v; ts += w; }
            }
            int coff = cs - c, toff = ts - nt;
            if (tid < E_NUM) {
                cur[tid] = coff;
                for (int j = 0; j < nt; j++) {
                    g_mt_e[toff + j]    = tid;
                    g_mt_base[toff + j] = coff + j * TM;
                    int rem = c - j * TM;
                    g_mt_cnt[toff + j]  = rem < TM ? rem : TM;
                }
                if (tid == E_NUM - 1) g_nmt = ts;
            }
        }
        __syncthreads();

        for (int t = tid; t < B_TOK; t += 256) {
            int e = route[t];
            unsigned m = __match_any_sync(0xffffffffu, e);
            int leader = __ffs(m) - 1;
            int rank = __popc(m & ((1u << lane) - 1u));
            int base = 0;
            if (lane == leader) base = atomicAdd(&cur[e], __popc(m));
            base = __shfl_sync(m, base, leader);
            g_sorted[base + rank] = t;
        }

        for (int i = tid; i < E_NUM * 256; i += 256)
            g_bsum[i] = bias[i] + bfact[i & 255];
    }
}

// ---------------------------------------------------------------------------
// gemm
// ---------------------------------------------------------------------------
__global__ __launch_bounds__(512, 1)
void switch_gemm(const float* __restrict__ input, float* __restrict__ out) {
    const int mt = blockIdx.x >> 1;
    const int nh = blockIdx.x & 1;            // 128-out half
    if (mt >= g_nmt) return;

    extern __shared__ float dsm[];
    float* const A_s[2] = { dsm, dsm + A_TILE_F };
    float* const B_s[3] = { dsm + 2 * A_TILE_F,
                            dsm + 2 * A_TILE_F + B_TILE_F,
                            dsm + 2 * A_TILE_F + 2 * B_TILE_F };
    __shared__ int   toks[TM];
    __shared__ float bias_s[TN];

    const int tid  = threadIdx.x;
    const int wid  = tid >> 5;
    const int lane = tid & 31;
    const int wm   = wid & 3;                  // rows wm*16..+15
    const int wn   = wid >> 2;                 // outs wn*32..+31 (within half)

    const int e     = g_mt_e[mt];
    const int tbase = g_mt_base[mt];
    const int tcnt  = g_mt_cnt[mt];

    if (tid < TM) {
        int i = (tid < tcnt) ? tid : (tcnt - 1);
        toks[tid] = g_sorted[tbase + i];
    }
    if (tid < TN) bias_s[tid] = g_bsum[e * 256 + nh * TN + tid];
    __syncthreads();

    // ---- staging roles (512 threads)
    const int ar = tid >> 3;                   // A row 0..63
    const int aq = tid & 7;                    // A float4 col (+8 for second)
    const int br = tid >> 2;                   // B row 0..127
    const int bq = tid & 3;                    // B 16B col (+4,+8,+12)
    const float* __restrict__ airow = input + (size_t)toks[ar] * 256;
    const float* __restrict__ wrow  = g_wsum + (size_t)e * 65536 + (size_t)(nh * TN + br) * 256;
    const uint32_t b_dst_base[3] = {
        smem_u32(B_s[0]) + (uint32_t)(br * RPAD + bq * 4) * 4,
        smem_u32(B_s[1]) + (uint32_t)(br * RPAD + bq * 4) * 4,
        smem_u32(B_s[2]) + (uint32_t)(br * RPAD + bq * 4) * 4 };

    auto cpB = [&](int c, int b) {             // 128 rows x 64 floats per chunk
        const float* src = wrow + c * KC + bq * 4;
        const uint32_t dst = b_dst_base[b];
        #pragma unroll
        for (int i = 0; i < 4; i++)
            CP_ASYNC16(dst + (uint32_t)(i * 16 * 4), src + i * 16);
        CP_COMMIT();
    };
    float4 rA0, rA1;
    auto ldgA = [&](int c) {
        rA0 = *(const float4*)(airow + c * KC + aq * 4);
        rA1 = *(const float4*)(airow + c * KC + (aq + 8) * 4);
    };
    auto stsA = [&](int b) {
        uint4 c0, c1;
        c0.x = f2tf(rA0.x); c0.y = f2tf(rA0.y); c0.z = f2tf(rA0.z); c0.w = f2tf(rA0.w);
        c1.x = f2tf(rA1.x); c1.y = f2tf(rA1.y); c1.z = f2tf(rA1.z); c1.w = f2tf(rA1.w);
        *(uint4*)(A_s[b] + ar * RPAD + aq * 4)       = c0;
        *(uint4*)(A_s[b] + ar * RPAD + (aq + 8) * 4) = c1;
    };

    // ---- ldmatrix lane addresses (byte offsets)
    const int a_off_l = ((wm * 16 + (lane & 15)) * RPAD + (lane >> 4) * 4) * 4;
    const int b_row_l = wn * 32 + ((lane >> 4) & 1) * 8 + (lane & 7);
    const int b_off_l = (b_row_l * RPAD + ((lane >> 3) & 1) * 4) * 4;
    const uint32_t A_u[2] = { smem_u32(A_s[0]) + a_off_l, smem_u32(A_s[1]) + a_off_l };
    const uint32_t B_u[3] = { smem_u32(B_s[0]) + b_off_l, smem_u32(B_s[1]) + b_off_l,
                              smem_u32(B_s[2]) + b_off_l };

    float acc[4][4];
    #pragma unroll
    for (int an = 0; an < 4; an++)
        #pragma unroll
        for (int j = 0; j < 4; j++) acc[an][j] = 0.0f;

    // prologue: B0,B1 in flight; A0 staged; A1 regs in flight
    cpB(0, 0);
    cpB(1, 1);
    ldgA(0);
    stsA(0);
    ldgA(1);

    #pragma unroll 1
    for (int c = 0; c < NCH; c++) {
        if (c < NCH - 1) CP_WAIT1(); else CP_WAIT0();   // cpB(c) landed (own)
        __syncthreads();            // everyone's cpB(c)+stsA(c) visible; compute(c-1) done
        if (c + 2 < NCH) cpB(c + 2, (c + 2) % 3);       // buf read by compute(c-1): done
        if (c + 1 < NCH) stsA((c + 1) & 1);             // buf read by compute(c-1): done
        if (c + 2 < NCH) ldgA(c + 2);

        const uint32_t Ab = A_u[c & 1];
        const uint32_t Bb = B_u[c % 3];
        #pragma unroll
        for (int kk = 0; kk < 8; kk++) {
            const uint32_t ko = kk * 32;       // kk*8 floats
            uint32_t a0[4], b0[4], b1r[4];
            LDSM_X4(a0[0], a0[1], a0[2], a0[3], Ab + ko);                     // m16
            LDSM_X4(b0[0], b0[1], b0[2], b0[3], Bb + ko);                     // n 0-15
            LDSM_X4(b1r[0], b1r[1], b1r[2], b1r[3], Bb + ko + 16 * RPAD * 4); // n 16-31
            mma_tf32(acc[0], a0, b0[0], b0[1]);
            mma_tf32(acc[1], a0, b0[2], b0[3]);
            mma_tf32(acc[2], a0, b1r[0], b1r[1]);
            mma_tf32(acc[3], a0, b1r[2], b1r[3]);
        }
    }

    // epilogue: bias + store
    const int row0 = wm * 16 + (lane >> 2);
    const int row1 = row0 + 8;
    const bool v0 = row0 < tcnt;
    const bool v1 = row1 < tcnt;
    float* const orow0 = out + (size_t)toks[row0] * 256 + nh * TN;
    float* const orow1 = out + (size_t)toks[row1] * 256 + nh * TN;
    #pragma unroll
    for (int an = 0; an < 4; an++) {
        const int col = wn * 32 + an * 8 + 2 * (lane & 3);
        const float bx = bias_s[col], by = bias_s[col + 1];
        if (v0) *(float2*)(orow0 + col) = make_float2(acc[an][0] + bx, acc[an][1] + by);
        if (v1) *(float2*)(orow1 + col) = make_float2(acc[an][2] + bx, acc[an][3] + by);
    }
}

// ---------------------------------------------------------------------------
extern "C" void kernel_launch(void* const* d_in, const int* in_sizes, int n_in,
                              void* d_out, int out_size) {
    const float* input  = (const float*)d_in[0];
    const int*   route  = (const int*)d_in[1];
    const float* weight = (const float*)d_in[2];
    const float* wfact  = (const float*)d_in[3];
    const float* bias   = (const float*)d_in[4];
    const float* bfact  = (const float*)d_in[5];
    float* out = (float*)d_out;

    cudaFuncSetAttribute(switch_gemm, cudaFuncAttributeMaxDynamicSharedMemorySize,
                         DSMEM_BYTES);

    prep_kernel<<<257, 256>>>(route, weight, wfact, bias, bfact);
    switch_gemm<<<GRID_GEMM, 512, DSMEM_BYTES>>>(input, out);
}

// round 13
// speedup vs baseline: 1.0011x; 1.0011x over previous
#include <cuda_runtime.h>
#include <cstdint>

// SwitchLinear via mma.sync tf32 + ldmatrix + cp.async (sm_103-safe PTX).
// out[t] = (W[route[t]] + Wf) @ x[t] + b[route[t]] + bf ; B=4096, IN=OUT=256, E=16.
//
// Algebraic split: out = W[e]@x + Wf@x + bias  (no weight pre-summing pass).
// route_kernel (1 block): routing into 64-token m-tiles + g_bsum = bias + bf.
// switch_gemm (<=160 blocks, 512 thr): tile = (64 tokens, 128 outs).
//   K-loop: 8 chunks of KC=64 — chunks 0-3 use W[e] rows, 4-7 use Wf rows,
//   same accumulators. A staged ONCE into 4 persistent smem buffers
//   (LDG + cvt.rna.tf32 + STS), reused for the Wf half. B streamed raw via
//   cp.async 3-buffer ring (HW truncates fp32->tf32). 16 warps (4m x 4n),
//   warp tile 16x32, fragments via ldmatrix.x4, rows padded to 68 floats.

#define B_TOK   4096
#define E_NUM   16
#define TM      64
#define TN      128
#define KC      64
#define NCH     8                         // 4 W-chunks + 4 Wf-chunks
#define MAX_MT  80
#define GRID_GEMM 160
#define RPAD    68                        // 64 + 4 pad floats per row
#define A_TILE_F (TM * RPAD)              // 4352 floats
#define B_TILE_F (TN * RPAD)              // 8704 floats
#define DSMEM_BYTES ((4 * A_TILE_F + 3 * B_TILE_F) * 4)   // 174080 B

__device__ int   g_sorted[B_TOK];
__device__ int   g_mt_e[MAX_MT];
__device__ int   g_mt_base[MAX_MT];
__device__ int   g_mt_cnt[MAX_MT];
__device__ int   g_nmt;
__device__ float g_bsum[E_NUM * 256];

static __device__ __forceinline__ uint32_t smem_u32(const void* p) {
    uint32_t a;
    asm("{ .reg .u64 t; cvta.to.shared.u64 t, %1; cvt.u32.u64 %0, t; }" : "=r"(a) : "l"(p));
    return a;
}
static __device__ __forceinline__ uint32_t f2tf(float x) {
    uint32_t u;
    asm("cvt.rna.tf32.f32 %0, %1;" : "=r"(u) : "f"(x));
    return u;
}
static __device__ __forceinline__ void mma_tf32(float* d, const uint32_t* a,
                                                uint32_t b0, uint32_t b1) {
    asm volatile(
        "mma.sync.aligned.m16n8k8.row.col.f32.tf32.tf32.f32 "
        "{%0,%1,%2,%3}, {%4,%5,%6,%7}, {%8,%9}, {%0,%1,%2,%3};"
        : "+f"(d[0]), "+f"(d[1]), "+f"(d[2]), "+f"(d[3])
        : "r"(a[0]), "r"(a[1]), "r"(a[2]), "r"(a[3]), "r"(b0), "r"(b1));
}
#define LDSM_X4(r0, r1, r2, r3, addr) \
    asm volatile("ldmatrix.sync.aligned.m8n8.x4.shared.b16 {%0,%1,%2,%3}, [%4];" \
                 : "=r"(r0), "=r"(r1), "=r"(r2), "=r"(r3) : "r"(addr))
#define CP_ASYNC16(dst, src) \
    asm volatile("cp.async.cg.shared.global [%0], [%1], 16;" :: "r"(dst), "l"(src))
#define CP_COMMIT() asm volatile("cp.async.commit_group;" ::: "memory")
#define CP_WAIT1()  asm volatile("cp.async.wait_group 1;" ::: "memory")
#define CP_WAIT0()  asm volatile("cp.async.wait_group 0;" ::: "memory")

// ---------------------------------------------------------------------------
// routing (1 block)
// ---------------------------------------------------------------------------
__global__ void route_kernel(const int* __restrict__ route,
                             const float* __restrict__ bias,
                             const float* __restrict__ bfact) {
    __shared__ int cnt[E_NUM];
    __shared__ int cur[E_NUM];
    const int tid  = threadIdx.x;
    const int lane = tid & 31;

    if (tid < E_NUM) cnt[tid] = 0;
    __syncthreads();

    for (int t = tid; t < B_TOK; t += 1024) {
        int e = route[t];
        unsigned m = __match_any_sync(0xffffffffu, e);
        int leader = __ffs(m) - 1;
        if (lane == leader) atomicAdd(&cnt[e], __popc(m));
    }
    __syncthreads();

    if (tid < 32) {
        int c  = (tid < E_NUM) ? cnt[tid] : 0;
        int nt = (c + TM - 1) / TM;
        int cs = c, ts = nt;
        #pragma unroll
        for (int d = 1; d < 32; d <<= 1) {
            int v = __shfl_up_sync(0xffffffffu, cs, d);
            int w = __shfl_up_sync(0xffffffffu, ts, d);
            if (lane >= d) { cs += v; ts += w; }
        }
        int coff = cs - c, toff = ts - nt;
        if (tid < E_NUM) {
            cur[tid] = coff;
            for (int j = 0; j < nt; j++) {
                g_mt_e[toff + j]    = tid;
                g_mt_base[toff + j] = coff + j * TM;
                int rem = c - j * TM;
                g_mt_cnt[toff + j]  = rem < TM ? rem : TM;
            }
            if (tid == E_NUM - 1) g_nmt = ts;
        }
    }
    __syncthreads();

    for (int t = tid; t < B_TOK; t += 1024) {
        int e = route[t];
        unsigned m = __match_any_sync(0xffffffffu, e);
        int leader = __ffs(m) - 1;
        int rank = __popc(m & ((1u << lane) - 1u));
        int base = 0;
        if (lane == leader) base = atomicAdd(&cur[e], __popc(m));
        base = __shfl_sync(m, base, leader);
        g_sorted[base + rank] = t;
    }

    for (int i = tid; i < E_NUM * 256; i += 1024)
        g_bsum[i] = bias[i] + bfact[i & 255];
}

// ---------------------------------------------------------------------------
// gemm
// ---------------------------------------------------------------------------
__global__ __launch_bounds__(512, 1)
void switch_gemm(const float* __restrict__ input,
                 const float* __restrict__ weight,
                 const float* __restrict__ wfact,
                 float* __restrict__ out) {
    const int mt = blockIdx.x >> 1;
    const int nh = blockIdx.x & 1;            // 128-out half
    if (mt >= g_nmt) return;

    extern __shared__ float dsm[];
    // floats: A0..A3 at 0,4352,8704,13056 ; B0..B2 at 17408,26112,34816
    float* const A_base = dsm;
    float* const B_base = dsm + 4 * A_TILE_F;
    __shared__ int   toks[TM];
    __shared__ float bias_s[TN];

    const int tid  = threadIdx.x;
    const int wid  = tid >> 5;
    const int lane = tid & 31;
    const int wm   = wid & 3;                  // rows wm*16..+15
    const int wn   = wid >> 2;                 // outs wn*32..+31 (within half)

    const int e     = g_mt_e[mt];
    const int tbase = g_mt_base[mt];
    const int tcnt  = g_mt_cnt[mt];

    if (tid < TM) {
        int i = (tid < tcnt) ? tid : (tcnt - 1);
        toks[tid] = g_sorted[tbase + i];
    }
    if (tid < TN) bias_s[tid] = g_bsum[e * 256 + nh * TN + tid];
    __syncthreads();

    // ---- staging roles (512 threads)
    const int ar = tid >> 3;                   // A row 0..63
    const int aq = tid & 7;                    // A float4 col (+8 for second)
    const int br = tid >> 2;                   // B row 0..127
    const int bq = tid & 3;                    // B 16B col
    const float* __restrict__ airow  = input + (size_t)toks[ar] * 256;
    const float* __restrict__ wrow_e = weight + (size_t)e * 65536 + (size_t)(nh * TN + br) * 256;
    const float* __restrict__ wrow_f = wfact + (size_t)(nh * TN + br) * 256;
    const uint32_t b_dst = smem_u32(B_base) + (uint32_t)(br * RPAD + bq * 4) * 4;

    auto cpB = [&](int c, int b) {             // 128 rows x 64 floats, raw fp32
        const float* src = ((c < 4) ? wrow_e : wrow_f) + (c & 3) * KC + bq * 4;
        const uint32_t dst = b_dst + (uint32_t)(b * B_TILE_F * 4);
        #pragma unroll
        for (int i = 0; i < 4; i++)
            CP_ASYNC16(dst + (uint32_t)(i * 16 * 4), src + i * 16);
        CP_COMMIT();
    };
    float4 rA0, rA1;
    auto ldgA = [&](int c) {
        rA0 = *(const float4*)(airow + c * KC + aq * 4);
        rA1 = *(const float4*)(airow + c * KC + (aq + 8) * 4);
    };
    auto stsA = [&](int b) {                   // rna-rounded A
        uint4 c0, c1;
        c0.x = f2tf(rA0.x); c0.y = f2tf(rA0.y); c0.z = f2tf(rA0.z); c0.w = f2tf(rA0.w);
        c1.x = f2tf(rA1.x); c1.y = f2tf(rA1.y); c1.z = f2tf(rA1.z); c1.w = f2tf(rA1.w);
        *(uint4*)(A_base + b * A_TILE_F + ar * RPAD + aq * 4)       = c0;
        *(uint4*)(A_base + b * A_TILE_F + ar * RPAD + (aq + 8) * 4) = c1;
    };

    // ---- ldmatrix lane addresses (byte offsets)
    const int a_off_l = ((wm * 16 + (lane & 15)) * RPAD + (lane >> 4) * 4) * 4;
    const int b_row_l = wn * 32 + ((lane >> 4) & 1) * 8 + (lane & 7);
    const int b_off_l = (b_row_l * RPAD + ((lane >> 3) & 1) * 4) * 4;
    uint32_t A_u[4], B_u[3];
    #pragma unroll
    for (int i = 0; i < 4; i++) A_u[i] = smem_u32(A_base + i * A_TILE_F) + a_off_l;
    #pragma unroll
    for (int i = 0; i < 3; i++) B_u[i] = smem_u32(B_base + i * B_TILE_F) + b_off_l;

    float acc[4][4];
    #pragma unroll
    for (int an = 0; an < 4; an++)
        #pragma unroll
        for (int j = 0; j < 4; j++) acc[an][j] = 0.0f;

    // prologue: B chunks 0,1 in flight; A chunk 0 staged; A chunk 1 in regs
    cpB(0, 0);
    cpB(1, 1);
    ldgA(0);
    stsA(0);
    ldgA(1);

    #pragma unroll 1
    for (int c = 0; c < NCH; c++) {
        if (c < NCH - 1) CP_WAIT1(); else CP_WAIT0();   // cpB(c) landed
        __syncthreads();       // cpB(c)+stsA(c) visible to all; compute(c-1) done
        if (c + 2 < NCH) cpB(c + 2, (c + 2) % 3);       // reuses buf of compute(c-1)
        if (c + 1 < 4)  stsA(c + 1);                    // A staged only in W half
        if (c + 2 < 4)  ldgA(c + 2);

        const uint32_t Ab = A_u[c & 3];                 // Wf half reuses A chunks
        const uint32_t Bb = B_u[c % 3];
        #pragma unroll
        for (int kk = 0; kk < 8; kk++) {
            const uint32_t ko = kk * 32;       // kk*8 floats
            uint32_t a0[4], b0[4], b1r[4];
            LDSM_X4(a0[0], a0[1], a0[2], a0[3], Ab + ko);                     // m16
            LDSM_X4(b0[0], b0[1], b0[2], b0[3], Bb + ko);                     // n 0-15
            LDSM_X4(b1r[0], b1r[1], b1r[2], b1r[3], Bb + ko + 16 * RPAD * 4); // n 16-31
            mma_tf32(acc[0], a0, b0[0], b0[1]);
            mma_tf32(acc[1], a0, b0[2], b0[3]);
            mma_tf32(acc[2], a0, b1r[0], b1r[1]);
            mma_tf32(acc[3], a0, b1r[2], b1r[3]);
        }
    }

    // epilogue: bias + store
    const int row0 = wm * 16 + (lane >> 2);
    const int row1 = row0 + 8;
    const bool v0 = row0 < tcnt;
    const bool v1 = row1 < tcnt;
    float* const orow0 = out + (size_t)toks[row0] * 256 + nh * TN;
    float* const orow1 = out + (size_t)toks[row1] * 256 + nh * TN;
    #pragma unroll
    for (int an = 0; an < 4; an++) {
        const int col = wn * 32 + an * 8 + 2 * (lane & 3);
        const float bx = bias_s[col], by = bias_s[col + 1];
        if (v0) *(float2*)(orow0 + col) = make_float2(acc[an][0] + bx, acc[an][1] + by);
        if (v1) *(float2*)(orow1 + col) = make_float2(acc[an][2] + bx, acc[an][3] + by);
    }
}

// ---------------------------------------------------------------------------
extern "C" void kernel_launch(void* const* d_in, const int* in_sizes, int n_in,
                              void* d_out, int out_size) {
    const float* input  = (const float*)d_in[0];
    const int*   route  = (const int*)d_in[1];
    const float* weight = (const float*)d_in[2];
    const float* wfact  = (const float*)d_in[3];
    const float* bias   = (const float*)d_in[4];
    const float* bfact  = (const float*)d_in[5];
    float* out = (float*)d_out;

    cudaFuncSetAttribute(switch_gemm, cudaFuncAttributeMaxDynamicSharedMemorySize,
                         DSMEM_BYTES);

    route_kernel<<<1, 1024>>>(route, bias, bfact);
    switch_gemm<<<GRID_GEMM, 512, DSMEM_BYTES>>>(input, weight, wfact, out);
}

// round 14
// speedup vs baseline: 1.0761x; 1.0749x over previous
#include <cuda_runtime.h>
#include <cstdint>

// SwitchLinear, SINGLE fused kernel: in-block routing + mma.sync tf32 GEMM.
// out[t] = (W[route[t]] + Wf) @ x[t] + b[route[t]] + bf ; B=4096, IN=OUT=256, E=16.
//
// Algebraic split: out = W[e]@x + Wf@x + bias (chunks 0-3 = W[e], 4-7 = Wf).
// Each block (mt, nq): 64 tokens x 64 outs. Routing computed redundantly per
// block: histogram (warp-aggregated) -> tile table walk (thread 0) -> block-wide
// binary rank-scan for this block's expert. 256 thr, 8 warps (4m x 2n),
// warp tile 16x32, m16n8k8.tf32, ldmatrix.x4 fragments, RPAD=68.
// B: cp.async 3-ring (raw fp32, HW-truncated). A: LDG+cvt.rna+STS 2-ring.
// 87 KB smem/CTA -> 2 CTAs/SM fill each other's barrier holes.

#define B_TOK   4096
#define E_NUM   16
#define TM      64
#define TN      64
#define KC      64
#define NCH     8
#define GRID_X  320                       // 4 quarters x MAX_MT(80)
#define RPAD    68
#define A_TILE_F (TM * RPAD)              // 4352 floats
#define B_TILE_F (TN * RPAD)              // 4352 floats
#define DSMEM_BYTES ((2 * A_TILE_F + 3 * B_TILE_F) * 4)   // 87040 B

static __device__ __forceinline__ uint32_t smem_u32(const void* p) {
    uint32_t a;
    asm("{ .reg .u64 t; cvta.to.shared.u64 t, %1; cvt.u32.u64 %0, t; }" : "=r"(a) : "l"(p));
    return a;
}
static __device__ __forceinline__ uint32_t f2tf(float x) {
    uint32_t u;
    asm("cvt.rna.tf32.f32 %0, %1;" : "=r"(u) : "f"(x));
    return u;
}
static __device__ __forceinline__ void mma_tf32(float* d, const uint32_t* a,
                                                uint32_t b0, uint32_t b1) {
    asm volatile(
        "mma.sync.aligned.m16n8k8.row.col.f32.tf32.tf32.f32 "
        "{%0,%1,%2,%3}, {%4,%5,%6,%7}, {%8,%9}, {%0,%1,%2,%3};"
        : "+f"(d[0]), "+f"(d[1]), "+f"(d[2]), "+f"(d[3])
        : "r"(a[0]), "r"(a[1]), "r"(a[2]), "r"(a[3]), "r"(b0), "r"(b1));
}
#define LDSM_X4(r0, r1, r2, r3, addr) \
    asm volatile("ldmatrix.sync.aligned.m8n8.x4.shared.b16 {%0,%1,%2,%3}, [%4];" \
                 : "=r"(r0), "=r"(r1), "=r"(r2), "=r"(r3) : "r"(addr))
#define CP_ASYNC16(dst, src) \
    asm volatile("cp.async.cg.shared.global [%0], [%1], 16;" :: "r"(dst), "l"(src))
#define CP_COMMIT() asm volatile("cp.async.commit_group;" ::: "memory")
#define CP_WAIT1()  asm volatile("cp.async.wait_group 1;" ::: "memory")
#define CP_WAIT0()  asm volatile("cp.async.wait_group 0;" ::: "memory")

__global__ __launch_bounds__(256, 2)
void switch_fused(const int* __restrict__ route,
                  const float* __restrict__ input,
                  const float* __restrict__ weight,
                  const float* __restrict__ wfact,
                  const float* __restrict__ bias,
                  const float* __restrict__ bfact,
                  float* __restrict__ out) {
    const int mt = blockIdx.x >> 2;
    const int nq = blockIdx.x & 3;             // 64-out quarter

    extern __shared__ float dsm[];
    float* const A_base = dsm;                           // 2 x A_TILE_F
    float* const B_base = dsm + 2 * A_TILE_F;            // 3 x B_TILE_F
    __shared__ int   cnt_s[E_NUM];
    __shared__ int   info_s[3];                // e, r0(rank base), tcnt
    __shared__ int   wexcl_s[8];
    __shared__ int   toks_s[TM];
    __shared__ float bias_s[TN];

    const int tid  = threadIdx.x;
    const int wid  = tid >> 5;
    const int lane = tid & 31;

    // ================= in-block routing =================
    int r[16];
    #pragma unroll
    for (int i = 0; i < 16; i++) r[i] = route[tid + 256 * i];

    if (tid < E_NUM) cnt_s[tid] = 0;
    if (tid < TM) toks_s[tid] = 0;             // padding rows -> token 0
    __syncthreads();

    #pragma unroll
    for (int i = 0; i < 16; i++) {
        int ei = r[i];
        unsigned m = __match_any_sync(0xffffffffu, ei);
        if ((__ffs(m) - 1) == lane) atomicAdd(&cnt_s[ei], __popc(m));
    }
    __syncthreads();

    if (tid == 0) {
        int tt = 0, found = -1, fr0 = 0, fcnt = 0;
        #pragma unroll
        for (int e2 = 0; e2 < E_NUM; e2++) {
            int c2 = cnt_s[e2];
            int nt = (c2 + TM - 1) >> 6;
            if (found < 0 && mt < tt + nt) {
                int j = mt - tt;
                found = e2;
                fr0 = j * TM;
                int rem = c2 - j * TM;
                fcnt = rem < TM ? rem : TM;
            }
            tt += nt;
        }
        info_s[0] = found; info_s[1] = fr0; info_s[2] = fcnt;
    }
    __syncthreads();

    const int e = info_s[0];
    if (e < 0) return;                          // uniform per block
    const int r0   = info_s[1];
    const int tcnt = info_s[2];

    // rank-scan over the binary indicator (route==e), order = (tid, i)
    int lc = 0;
    #pragma unroll
    for (int i = 0; i < 16; i++) lc += (r[i] == e) ? 1 : 0;
    int sc = lc;
    #pragma unroll
    for (int d = 1; d < 32; d <<= 1) {
        int v = __shfl_up_sync(0xffffffffu, sc, d);
        if (lane >= d) sc += v;
    }
    if (lane == 31) wexcl_s[wid] = sc;
    __syncthreads();
    if (tid == 0) {
        int acc = 0;
        #pragma unroll
        for (int w = 0; w < 8; w++) { int v = wexcl_s[w]; wexcl_s[w] = acc; acc += v; }
    }
    __syncthreads();
    int rank = (sc - lc) + wexcl_s[wid];        // exclusive prefix for this thread
    #pragma unroll
    for (int i = 0; i < 16; i++) {
        if (r[i] == e) {
            int rr = rank - r0;
            if (rr >= 0 && rr < TM) toks_s[rr] = tid + 256 * i;
            rank++;
        }
    }
    if (tid < TN)
        bias_s[tid] = bias[e * 256 + nq * TN + tid] + bfact[nq * TN + tid];
    __syncthreads();

    // ================= GEMM =================
    const int wm = wid & 3;                    // rows wm*16..+15
    const int wn = wid >> 2;                   // outs wn*32..+31 (within quarter)

    // staging roles (256 threads): row = tid>>2, quad q = tid&3 (cols q*4 + j*16)
    const int srow = tid >> 2;
    const int sq   = tid & 3;
    const float* __restrict__ airow  = input + (size_t)toks_s[srow] * 256;
    const float* __restrict__ wrow_e = weight + (size_t)e * 65536 + (size_t)(nq * TN + srow) * 256;
    const float* __restrict__ wrow_f = wfact + (size_t)(nq * TN + srow) * 256;
    const uint32_t b_dst = smem_u32(B_base) + (uint32_t)((srow * RPAD + sq * 4) * 4);

    auto cpB = [&](int c, int b) {             // 64 rows x 64 floats, raw fp32
        const float* src = ((c < 4) ? wrow_e : wrow_f) + (c & 3) * KC + sq * 4;
        const uint32_t dst = b_dst + (uint32_t)(b * B_TILE_F * 4);
        #pragma unroll
        for (int j = 0; j < 4; j++)
            CP_ASYNC16(dst + (uint32_t)(j * 16 * 4), src + j * 16);
        CP_COMMIT();
    };
    float4 rA[4];
    auto ldgA = [&](int c) {                   // input chunk (c&3)
        #pragma unroll
        for (int j = 0; j < 4; j++)
            rA[j] = *(const float4*)(airow + (c & 3) * KC + sq * 4 + j * 16);
    };
    auto stsA = [&](int b) {                   // rna-rounded A
        #pragma unroll
        for (int j = 0; j < 4; j++) {
            uint4 cv;
            cv.x = f2tf(rA[j].x); cv.y = f2tf(rA[j].y);
            cv.z = f2tf(rA[j].z); cv.w = f2tf(rA[j].w);
            *(uint4*)(A_base + b * A_TILE_F + srow * RPAD + sq * 4 + j * 16) = cv;
        }
    };

    // ldmatrix lane addresses (byte offsets)
    const int a_off_l = ((wm * 16 + (lane & 15)) * RPAD + (lane >> 4) * 4) * 4;
    const int b_row_l = wn * 32 + ((lane >> 4) & 1) * 8 + (lane & 7);
    const int b_off_l = (b_row_l * RPAD + ((lane >> 3) & 1) * 4) * 4;
    uint32_t A_u[2], B_u[3];
    #pragma unroll
    for (int i = 0; i < 2; i++) A_u[i] = smem_u32(A_base + i * A_TILE_F) + a_off_l;
    #pragma unroll
    for (int i = 0; i < 3; i++) B_u[i] = smem_u32(B_base + i * B_TILE_F) + b_off_l;

    float acc[4][4];
    #pragma unroll
    for (int an = 0; an < 4; an++)
        #pragma unroll
        for (int j = 0; j < 4; j++) acc[an][j] = 0.0f;

    // prologue
    cpB(0, 0);
    cpB(1, 1);
    ldgA(0);
    stsA(0);
    ldgA(1);

    #pragma unroll 1
    for (int c = 0; c < NCH; c++) {
        if (c < NCH - 1) CP_WAIT1(); else CP_WAIT0();   // cpB(c) landed
        __syncthreads();        // cpB(c)+stsA(c) visible; compute(c-1) done
        if (c + 2 < NCH) cpB(c + 2, (c + 2) % 3);       // buf freed by compute(c-1)
        if (c + 1 < NCH) stsA((c + 1) & 1);             // buf freed by compute(c-1)
        if (c + 2 < NCH) ldgA(c + 2);

        const uint32_t Ab = A_u[c & 1];
        const uint32_t Bb = B_u[c % 3];
        #pragma unroll
        for (int kk = 0; kk < 8; kk++) {
            const uint32_t ko = kk * 32;       // kk*8 floats
            uint32_t a0[4], b0[4], b1r[4];
            LDSM_X4(a0[0], a0[1], a0[2], a0[3], Ab + ko);                     // m16
            LDSM_X4(b0[0], b0[1], b0[2], b0[3], Bb + ko);                     // n 0-15
            LDSM_X4(b1r[0], b1r[1], b1r[2], b1r[3], Bb + ko + 16 * RPAD * 4); // n 16-31
            mma_tf32(acc[0], a0, b0[0], b0[1]);
            mma_tf32(acc[1], a0, b0[2], b0[3]);
            mma_tf32(acc[2], a0, b1r[0], b1r[1]);
            mma_tf32(acc[3], a0, b1r[2], b1r[3]);
        }
    }

    // epilogue: bias + store
    const int row0 = wm * 16 + (lane >> 2);
    const int row1 = row0 + 8;
    const bool v0 = row0 < tcnt;
    const bool v1 = row1 < tcnt;
    float* const orow0 = out + (size_t)toks_s[row0] * 256 + nq * TN;
    float* const orow1 = out + (size_t)toks_s[row1] * 256 + nq * TN;
    #pragma unroll
    for (int an = 0; an < 4; an++) {
        const int col = wn * 32 + an * 8 + 2 * (lane & 3);
        const float bx = bias_s[col], by = bias_s[col + 1];
        if (v0) *(float2*)(orow0 + col) = make_float2(acc[an][0] + bx, acc[an][1] + by);
        if (v1) *(float2*)(orow1 + col) = make_float2(acc[an][2] + bx, acc[an][3] + by);
    }
}

// ---------------------------------------------------------------------------
extern "C" void kernel_launch(void* const* d_in, const int* in_sizes, int n_in,
                              void* d_out, int out_size) {
    const float* input  = (const float*)d_in[0];
    const int*   route  = (const int*)d_in[1];
    const float* weight = (const float*)d_in[2];
    const float* wfact  = (const float*)d_in[3];
    const float* bias   = (const float*)d_in[4];
    const float* bfact  = (const float*)d_in[5];
    float* out = (float*)d_out;

    cudaFuncSetAttribute(switch_fused, cudaFuncAttributeMaxDynamicSharedMemorySize,
                         DSMEM_BYTES);

    switch_fused<<<GRID_X, 256, DSMEM_BYTES>>>(route, input, weight, wfact,
                                               bias, bfact, out);
}

// round 15
// speedup vs baseline: 1.2641x; 1.1747x over previous
#include <cuda_runtime.h>
#include <cstdint>

// SwitchLinear, SINGLE fused kernel: in-block routing + mma.sync tf32 GEMM.
// out[t] = (W[route[t]] + Wf) @ x[t] + b[route[t]] + bf ; B=4096, IN=OUT=256, E=16.
//
// Algebraic split with PAIRED stages: stage s (KC=64) loads BOTH the W[e] and
// Wf B-tiles under one cp.async group, computes 16 k-steps per barrier (8 W +
// 8 Wf) reusing the SAME A fragments. 4 barriers total (was 8).
// Block (mt, nq) = 64 tokens x 64 outs; 256 thr, 8 warps (4m x 2n),
// warp tile 16x32, m16n8k8.tf32, ldmatrix.x4, RPAD=68.
// smem = 2xA + 4xB = 104448 B -> 2 CTAs/SM fill each other's barrier holes.

#define B_TOK   4096
#define E_NUM   16
#define TM      64
#define TN      64
#define KC      64
#define NST     4                         // paired stages
#define GRID_X  320                       // 4 quarters x max 80 m-tiles
#define RPAD    68
#define A_TILE_F (TM * RPAD)              // 4352 floats
#define B_TILE_F (TN * RPAD)              // 4352 floats
#define DSMEM_BYTES ((2 * A_TILE_F + 4 * B_TILE_F) * 4)   // 104448 B

static __device__ __forceinline__ uint32_t smem_u32(const void* p) {
    uint32_t a;
    asm("{ .reg .u64 t; cvta.to.shared.u64 t, %1; cvt.u32.u64 %0, t; }" : "=r"(a) : "l"(p));
    return a;
}
static __device__ __forceinline__ uint32_t f2tf(float x) {
    uint32_t u;
    asm("cvt.rna.tf32.f32 %0, %1;" : "=r"(u) : "f"(x));
    return u;
}
static __device__ __forceinline__ void mma_tf32(float* d, const uint32_t* a,
                                                uint32_t b0, uint32_t b1) {
    asm volatile(
        "mma.sync.aligned.m16n8k8.row.col.f32.tf32.tf32.f32 "
        "{%0,%1,%2,%3}, {%4,%5,%6,%7}, {%8,%9}, {%0,%1,%2,%3};"
        : "+f"(d[0]), "+f"(d[1]), "+f"(d[2]), "+f"(d[3])
        : "r"(a[0]), "r"(a[1]), "r"(a[2]), "r"(a[3]), "r"(b0), "r"(b1));
}
#define LDSM_X4(r0, r1, r2, r3, addr) \
    asm volatile("ldmatrix.sync.aligned.m8n8.x4.shared.b16 {%0,%1,%2,%3}, [%4];" \
                 : "=r"(r0), "=r"(r1), "=r"(r2), "=r"(r3) : "r"(addr))
#define CP_ASYNC16(dst, src) \
    asm volatile("cp.async.cg.shared.global [%0], [%1], 16;" :: "r"(dst), "l"(src))
#define CP_COMMIT() asm volatile("cp.async.commit_group;" ::: "memory")
#define CP_WAIT0()  asm volatile("cp.async.wait_group 0;" ::: "memory")

__global__ __launch_bounds__(256, 2)
void switch_fused(const int* __restrict__ route,
                  const float* __restrict__ input,
                  const float* __restrict__ weight,
                  const float* __restrict__ wfact,
                  const float* __restrict__ bias,
                  const float* __restrict__ bfact,
                  float* __restrict__ out) {
    const int mt = blockIdx.x >> 2;
    const int nq = blockIdx.x & 3;             // 64-out quarter

    extern __shared__ float dsm[];
    float* const A_base = dsm;                           // 2 x A_TILE_F
    float* const B_base = dsm + 2 * A_TILE_F;            // 4 x B_TILE_F (W0,W1,F0,F1)
    __shared__ int   cnt_s[E_NUM];
    __shared__ int   info_s[3];                // e, r0(rank base), tcnt
    __shared__ int   wexcl_s[8];
    __shared__ int   toks_s[TM];
    __shared__ float bias_s[TN];

    const int tid  = threadIdx.x;
    const int wid  = tid >> 5;
    const int lane = tid & 31;

    // ================= in-block routing (verified R14) =================
    int r[16];
    #pragma unroll
    for (int i = 0; i < 16; i++) r[i] = route[tid + 256 * i];

    if (tid < E_NUM) cnt_s[tid] = 0;
    if (tid < TM) toks_s[tid] = 0;             // padding rows -> token 0
    __syncthreads();

    #pragma unroll
    for (int i = 0; i < 16; i++) {
        int ei = r[i];
        unsigned m = __match_any_sync(0xffffffffu, ei);
        if ((__ffs(m) - 1) == lane) atomicAdd(&cnt_s[ei], __popc(m));
    }
    __syncthreads();

    if (tid == 0) {
        int tt = 0, found = -1, fr0 = 0, fcnt = 0;
        #pragma unroll
        for (int e2 = 0; e2 < E_NUM; e2++) {
            int c2 = cnt_s[e2];
            int nt = (c2 + TM - 1) >> 6;
            if (found < 0 && mt < tt + nt) {
                int j = mt - tt;
                found = e2;
                fr0 = j * TM;
                int rem = c2 - j * TM;
                fcnt = rem < TM ? rem : TM;
            }
            tt += nt;
        }
        info_s[0] = found; info_s[1] = fr0; info_s[2] = fcnt;
    }
    __syncthreads();

    const int e = info_s[0];
    if (e < 0) return;                          // uniform per block
    const int r0   = info_s[1];
    const int tcnt = info_s[2];

    int lc = 0;
    #pragma unroll
    for (int i = 0; i < 16; i++) lc += (r[i] == e) ? 1 : 0;
    int sc = lc;
    #pragma unroll
    for (int d = 1; d < 32; d <<= 1) {
        int v = __shfl_up_sync(0xffffffffu, sc, d);
        if (lane >= d) sc += v;
    }
    if (lane == 31) wexcl_s[wid] = sc;
    __syncthreads();
    if (tid == 0) {
        int acc2 = 0;
        #pragma unroll
        for (int w = 0; w < 8; w++) { int v = wexcl_s[w]; wexcl_s[w] = acc2; acc2 += v; }
    }
    __syncthreads();
    int rank = (sc - lc) + wexcl_s[wid];
    #pragma unroll
    for (int i = 0; i < 16; i++) {
        if (r[i] == e) {
            int rr = rank - r0;
            if (rr >= 0 && rr < TM) toks_s[rr] = tid + 256 * i;
            rank++;
        }
    }
    if (tid < TN)
        bias_s[tid] = bias[e * 256 + nq * TN + tid] + bfact[nq * TN + tid];
    __syncthreads();

    // ================= GEMM =================
    const int wm = wid & 3;                    // rows wm*16..+15
    const int wn = wid >> 2;                   // outs wn*32..+31 (within quarter)

    const int srow = tid >> 2;                 // staging row 0..63
    const int sq   = tid & 3;                  // 16B quad
    const float* __restrict__ airow  = input + (size_t)toks_s[srow] * 256;
    const float* __restrict__ wrow_e = weight + (size_t)e * 65536 + (size_t)(nq * TN + srow) * 256;
    const float* __restrict__ wrow_f = wfact + (size_t)(nq * TN + srow) * 256;
    const uint32_t b_dst = smem_u32(B_base) + (uint32_t)((srow * RPAD + sq * 4) * 4);

    // stage s: load W[e] chunk s -> BW buf b, Wf chunk s -> BF buf b (one group)
    auto cpB = [&](int s, int b) {
        const float* srcW = wrow_e + s * KC + sq * 4;
        const float* srcF = wrow_f + s * KC + sq * 4;
        const uint32_t dstW = b_dst + (uint32_t)(b * B_TILE_F * 4);
        const uint32_t dstF = b_dst + (uint32_t)((2 + b) * B_TILE_F * 4);
        #pragma unroll
        for (int j = 0; j < 4; j++)
            CP_ASYNC16(dstW + (uint32_t)(j * 16 * 4), srcW + j * 16);
        #pragma unroll
        for (int j = 0; j < 4; j++)
            CP_ASYNC16(dstF + (uint32_t)(j * 16 * 4), srcF + j * 16);
        CP_COMMIT();
    };
    float4 rA[4];
    auto ldgA = [&](int c) {
        #pragma unroll
        for (int j = 0; j < 4; j++)
            rA[j] = *(const float4*)(airow + c * KC + sq * 4 + j * 16);
    };
    auto stsA = [&](int b) {                   // rna-rounded A
        #pragma unroll
        for (int j = 0; j < 4; j++) {
            uint4 cv;
            cv.x = f2tf(rA[j].x); cv.y = f2tf(rA[j].y);
            cv.z = f2tf(rA[j].z); cv.w = f2tf(rA[j].w);
            *(uint4*)(A_base + b * A_TILE_F + srow * RPAD + sq * 4 + j * 16) = cv;
        }
    };

    // ldmatrix lane addresses (byte offsets)
    const int a_off_l = ((wm * 16 + (lane & 15)) * RPAD + (lane >> 4) * 4) * 4;
    const int b_row_l = wn * 32 + ((lane >> 4) & 1) * 8 + (lane & 7);
    const int b_off_l = (b_row_l * RPAD + ((lane >> 3) & 1) * 4) * 4;
    uint32_t A_u[2], B_u[4];
    #pragma unroll
    for (int i = 0; i < 2; i++) A_u[i] = smem_u32(A_base + i * A_TILE_F) + a_off_l;
    #pragma unroll
    for (int i = 0; i < 4; i++) B_u[i] = smem_u32(B_base + i * B_TILE_F) + b_off_l;

    float acc[4][4];
    #pragma unroll
    for (int an = 0; an < 4; an++)
        #pragma unroll
        for (int j = 0; j < 4; j++) acc[an][j] = 0.0f;

    // prologue: stage 0 B pair in flight; A chunk 0 staged; A chunk 1 in regs
    cpB(0, 0);
    ldgA(0);
    stsA(0);
    ldgA(1);

    #pragma unroll 1
    for (int s = 0; s < NST; s++) {
        CP_WAIT0();                 // B pair (s) landed
        __syncthreads();            // + stsA(s) visible; compute(s-1) done
        if (s + 1 < NST) {
            cpB(s + 1, (s + 1) & 1);     // B bufs freed by compute(s-1)
            stsA((s + 1) & 1);           // A buf freed by compute(s-1)
        }
        if (s + 2 < NST) ldgA(s + 2);

        const uint32_t Ab = A_u[s & 1];
        const uint32_t BW = B_u[s & 1];
        const uint32_t BF = B_u[2 + (s & 1)];
        #pragma unroll
        for (int kk = 0; kk < 8; kk++) {
            const uint32_t ko = kk * 32;       // kk*8 floats
            uint32_t a0[4], w0[4], w1[4], f0[4], f1[4];
            LDSM_X4(a0[0], a0[1], a0[2], a0[3], Ab + ko);                    // m16
            LDSM_X4(w0[0], w0[1], w0[2], w0[3], BW + ko);                    // W n0-15
            LDSM_X4(w1[0], w1[1], w1[2], w1[3], BW + ko + 16 * RPAD * 4);    // W n16-31
            mma_tf32(acc[0], a0, w0[0], w0[1]);
            mma_tf32(acc[1], a0, w0[2], w0[3]);
            mma_tf32(acc[2], a0, w1[0], w1[1]);
            mma_tf32(acc[3], a0, w1[2], w1[3]);
            LDSM_X4(f0[0], f0[1], f0[2], f0[3], BF + ko);                    // Wf n0-15
            LDSM_X4(f1[0], f1[1], f1[2], f1[3], BF + ko + 16 * RPAD * 4);    // Wf n16-31
            mma_tf32(acc[0], a0, f0[0], f0[1]);
            mma_tf32(acc[1], a0, f0[2], f0[3]);
            mma_tf32(acc[2], a0, f1[0], f1[1]);
            mma_tf32(acc[3], a0, f1[2], f1[3]);
        }
    }

    // epilogue: bias + store
    const int row0 = wm * 16 + (lane >> 2);
    const int row1 = row0 + 8;
    const bool v0 = row0 < tcnt;
    const bool v1 = row1 < tcnt;
    float* const orow0 = out + (size_t)toks_s[row0] * 256 + nq * TN;
    float* const orow1 = out + (size_t)toks_s[row1] * 256 + nq * TN;
    #pragma unroll
    for (int an = 0; an < 4; an++) {
        const int col = wn * 32 + an * 8 + 2 * (lane & 3);
        const float bx = bias_s[col], by = bias_s[col + 1];
        if (v0) *(float2*)(orow0 + col) = make_float2(acc[an][0] + bx, acc[an][1] + by);
        if (v1) *(float2*)(orow1 + col) = make_float2(acc[an][2] + bx, acc[an][3] + by);
    }
}

// ---------------------------------------------------------------------------
extern "C" void kernel_launch(void* const* d_in, const int* in_sizes, int n_in,
                              void* d_out, int out_size) {
    const float* input  = (const float*)d_in[0];
    const int*   route  = (const int*)d_in[1];
    const float* weight = (const float*)d_in[2];
    const float* wfact  = (const float*)d_in[3];
    const float* bias   = (const float*)d_in[4];
    const float* bfact  = (const float*)d_in[5];
    float* out = (float*)d_out;

    cudaFuncSetAttribute(switch_fused, cudaFuncAttributeMaxDynamicSharedMemorySize,
                         DSMEM_BYTES);

    switch_fused<<<GRID_X, 256, DSMEM_BYTES>>>(route, input, weight, wfact,
                                               bias, bfact, out);
}